// round 3
// baseline (speedup 1.0000x reference)
#include <cuda_runtime.h>
#include <math.h>

#define NB 16
#define NT 32
#define NTARG (NB*NT)      // 512
#define NAq 3
#define NCLS 80
#define CELLS0 (16*3*64*64)   // 196608
#define CELLS1 (16*3*32*32)   // 49152
#define CELLS2 (16*3*16*16)   // 12288
#define TOTAL_CELLS (CELLS0+CELLS1+CELLS2)  // 258048

__device__ unsigned char g_flags[TOTAL_CELLS];
__device__ float g_acc[12];     // cnt[0..2], box[3..5], cls[6..8], obj[9..11]
__device__ unsigned int g_done;

__device__ __forceinline__ float softplusf(float x) {
    return fmaxf(x, 0.0f) + log1pf(expf(-fabsf(x)));
}
__device__ __forceinline__ float sigmoidf(float x) {
    return 1.0f / (1.0f + expf(-x));
}

// ---------------------------------------------------------------------------
// K0: zero scratch
// ---------------------------------------------------------------------------
__global__ void k_zero() {
    int i = blockIdx.x * blockDim.x + threadIdx.x;
    const int n16 = TOTAL_CELLS / 16;  // 16128 uint4 writes, exact
    uint4 z = make_uint4(0u, 0u, 0u, 0u);
    for (int j = i; j < n16; j += gridDim.x * blockDim.x)
        reinterpret_cast<uint4*>(g_flags)[j] = z;
    if (blockIdx.x == 0) {
        if (threadIdx.x < 12) g_acc[threadIdx.x] = 0.0f;
        if (threadIdx.x == 0) g_done = 0u;
    }
}

// ---------------------------------------------------------------------------
// K1: one warp per (target, scale). Match anchors, scatter flags, accumulate
//     cnt / box-loss-sum / cls-loss-sum (undivided; divided in final fold).
// ---------------------------------------------------------------------------
__global__ void k_targets(const float* __restrict__ inf0,
                          const float* __restrict__ inf1,
                          const float* __restrict__ inf2,
                          const float* __restrict__ anchors,
                          const float* __restrict__ strides,
                          const float* __restrict__ targets)
{
    int gw = (blockIdx.x * blockDim.x + threadIdx.x) >> 5;
    int lane = threadIdx.x & 31;
    if (gw >= NTARG * 3) return;
    int t = gw / 3;
    int s = gw - t * 3;

    const float* inf = (s == 0) ? inf0 : (s == 1) ? inf1 : inf2;
    int g = 64 >> s;
    float str = strides[s];
    int cell_off = (s == 0) ? 0 : (s == 1) ? CELLS0 : (CELLS0 + CELLS1);

    float x  = targets[t * 5 + 0];
    float y  = targets[t * 5 + 1];
    float w  = targets[t * 5 + 2];
    float h  = targets[t * 5 + 3];
    int  cls = (int)targets[t * 5 + 4];
    int  b   = t / NT;

    float tx = x / str, ty = y / str;
    float cif = floorf(tx), cjf = floorf(ty);
    int ci = (int)cif, cj = (int)cjf;
    float fx = tx - cif, fy = ty - cjf;
    float tw = w / str, th = h / str;

    // target rect (grid units, centered at fractional offset)
    float t_x0 = fx - 0.5f * tw, t_y0 = fy - 0.5f * th;
    float t_x1 = fx + 0.5f * tw, t_y1 = fy + 0.5f * th;
    float t_area = tw * th;

    float boxsum = 0.0f;   // lane 0 only
    float clssum = 0.0f;   // distributed across lanes
    int   cntloc = 0;

    for (int a = 0; a < NAq; a++) {
        float aw = anchors[(s * NAq + a) * 2 + 0] / str;
        float ah = anchors[(s * NAq + a) * 2 + 1] / str;

        // anchor rect centered at (0.5, 0.5)
        float a_x0 = 0.5f - 0.5f * aw, a_y0 = 0.5f - 0.5f * ah;
        float a_x1 = 0.5f + 0.5f * aw, a_y1 = 0.5f + 0.5f * ah;

        float x0 = fmaxf(t_x0, a_x0), y0 = fmaxf(t_y0, a_y0);
        float x1 = fminf(t_x1, a_x1), y1 = fminf(t_y1, a_y1);
        float inter = (x0 < x1 && y0 < y1) ? (x1 - x0) * (y1 - y0) : 0.0f;
        float iou_ta = inter / (t_area + aw * ah - inter);
        if (!(iou_ta > 0.5f)) continue;   // uniform across warp (all inputs uniform)

        cntloc++;
        const float* pred = inf + ((((long)b * NAq + a) * g + cj) * g + ci) * 85;

        if (lane == 0) {
            g_flags[cell_off + ((b * NAq + a) * g + cj) * g + ci] = 1;

            // box loss term: 1 - IoU(pred_box, target_box)
            float p0 = pred[0], p1 = pred[1], p2 = pred[2], p3 = pred[3];
            float pxc = sigmoidf(p0), pyc = sigmoidf(p1);
            float pw = fminf(expf(p2), 1000.0f) * aw;
            float ph = fminf(expf(p3), 1000.0f) * ah;
            float p_x0 = pxc - 0.5f * pw, p_y0 = pyc - 0.5f * ph;
            float p_x1 = pxc + 0.5f * pw, p_y1 = pyc + 0.5f * ph;
            float ix0 = fmaxf(p_x0, t_x0), iy0 = fmaxf(p_y0, t_y0);
            float ix1 = fminf(p_x1, t_x1), iy1 = fminf(p_y1, t_y1);
            float pint = (ix0 < ix1 && iy0 < iy1) ? (ix1 - ix0) * (iy1 - iy0) : 0.0f;
            float uni = pw * ph + t_area - pint;
            boxsum += 1.0f - pint / uni;
        }

        // cls BCE: 80 classes spread across lanes (lane, lane+32, lane+64)
        #pragma unroll
        for (int k = 0; k < 3; k++) {
            int c = lane + k * 32;
            if (c < NCLS) {
                float p = pred[5 + c];
                clssum += (c == cls) ? softplusf(-p) : softplusf(p);
            }
        }
    }

    // warp-reduce cls sum
    #pragma unroll
    for (int o = 16; o; o >>= 1)
        clssum += __shfl_xor_sync(0xFFFFFFFFu, clssum, o);

    if (lane == 0 && cntloc > 0) {
        atomicAdd(&g_acc[s],     (float)cntloc);
        atomicAdd(&g_acc[3 + s], boxsum);
        atomicAdd(&g_acc[6 + s], clssum);
    }
}

// ---------------------------------------------------------------------------
// K2: objectness BCE over all 258,048 cells + last-block final fold.
// ---------------------------------------------------------------------------
__global__ void k_obj(const float* __restrict__ inf0,
                      const float* __restrict__ inf1,
                      const float* __restrict__ inf2,
                      float* __restrict__ out)
{
    __shared__ float sh[3];
    if (threadIdx.x < 3) sh[threadIdx.x] = 0.0f;
    __syncthreads();

    int stride = gridDim.x * blockDim.x;
    for (int idx = blockIdx.x * blockDim.x + threadIdx.x; idx < TOTAL_CELLS; idx += stride) {
        int s, cell;
        const float* inf;
        if (idx < CELLS0)                { s = 0; cell = idx;                     inf = inf0; }
        else if (idx < CELLS0 + CELLS1)  { s = 1; cell = idx - CELLS0;            inf = inf1; }
        else                             { s = 2; cell = idx - (CELLS0 + CELLS1); inf = inf2; }

        float p = inf[(long)cell * 85 + 4];
        float bce = g_flags[idx] ? softplusf(-p) : softplusf(p);
        // reduce within warp first where s is uniform; here just shared atomics
        atomicAdd(&sh[s], bce);
    }
    __syncthreads();

    if (threadIdx.x == 0) {
        #pragma unroll
        for (int s = 0; s < 3; s++)
            if (sh[s] != 0.0f) atomicAdd(&g_acc[9 + s], sh[s]);
        __threadfence();
        unsigned int d = atomicAdd(&g_done, 1u);
        if (d == gridDim.x - 1) {
            __threadfence();
            const float cells[3] = {(float)CELLS0, (float)CELLS1, (float)CELLS2};
            float box = 0.0f, obj = 0.0f, clsv = 0.0f;
            #pragma unroll
            for (int s = 0; s < 3; s++) {
                float cnt = fmaxf(g_acc[s], 1.0f);
                box  += g_acc[3 + s] / cnt;
                clsv += g_acc[6 + s] / (cnt * (float)NCLS);
                obj  += g_acc[9 + s] / cells[s];
            }
            out[0] = 3.54f * box + 64.3f * obj + 37.4f * clsv;
        }
    }
}

// ---------------------------------------------------------------------------
extern "C" void kernel_launch(void* const* d_in, const int* in_sizes, int n_in,
                              void* d_out, int out_size)
{
    const float* inf0    = (const float*)d_in[0];
    const float* inf1    = (const float*)d_in[1];
    const float* inf2    = (const float*)d_in[2];
    const float* anchors = (const float*)d_in[3];
    const float* strides = (const float*)d_in[4];
    const float* targets = (const float*)d_in[5];
    float* out = (float*)d_out;

    k_zero<<<63, 256>>>();
    k_targets<<<(NTARG * 3 * 32 + 127) / 128, 128>>>(inf0, inf1, inf2, anchors, strides, targets);
    k_obj<<<(TOTAL_CELLS + 255) / 256, 256>>>(inf0, inf1, inf2, out);
}

// round 4
// speedup vs baseline: 1.9955x; 1.9955x over previous
#include <cuda_runtime.h>
#include <math.h>

#define NB 16
#define NT 32
#define NAq 3
#define NCLS 80
#define CELLS0 196608   // 16*3*64*64
#define CELLS1 49152    // 16*3*32*32
#define CELLS2 12288    // 16*3*16*16
#define NBLOCKS 192
#define BLK 256
#define NTHREADS (NBLOCKS*BLK)   // 49152 == CELLS1, == CELLS0/4

__device__ float g_acc[12];      // cnt[0..2], box[3..5], cls[6..8], obj[9..11]
__device__ unsigned int g_done;

__device__ __forceinline__ float softplusf(float x) {
    return fmaxf(x, 0.0f) + log1pf(expf(-fabsf(x)));
}
__device__ __forceinline__ float sigmoidf(float x) {
    return 1.0f / (1.0f + expf(-x));
}

__global__ void __launch_bounds__(BLK) yolo_fused(
    const float* __restrict__ inf0, const float* __restrict__ inf1,
    const float* __restrict__ inf2, const float* __restrict__ anchors,
    const float* __restrict__ strides, const float* __restrict__ targets,
    float* __restrict__ out)
{
    const unsigned FULL = 0xFFFFFFFFu;
    int tid  = blockIdx.x * BLK + threadIdx.x;
    int lane = threadIdx.x & 31;

    // ================= objectness baseline sweep (no flags needed) =========
    // exactly 4 + 1 + (tid<CELLS2) strided loads per thread, all independent
    float a0 = inf0[(long)(tid             ) * 85 + 4];
    float a1 = inf0[(long)(tid +   NTHREADS) * 85 + 4];
    float a2 = inf0[(long)(tid + 2*NTHREADS) * 85 + 4];
    float a3 = inf0[(long)(tid + 3*NTHREADS) * 85 + 4];
    float b0 = inf1[(long)tid * 85 + 4];
    float obj2 = 0.0f;
    if (tid < CELLS2) obj2 = softplusf(inf2[(long)tid * 85 + 4]);
    float obj0 = (softplusf(a0) + softplusf(a1)) + (softplusf(a2) + softplusf(a3));
    float obj1 = softplusf(b0);

    // ================= per-(target,scale) work: one warp per item ==========
    // total warps == 1536 == 512 targets * 3 scales, exactly one item each
    {
        int gw = tid >> 5;               // 0..1535
        int t  = gw / 3;
        int s  = gw - t * 3;
        int b  = t >> 5;
        int t_local = t & 31;

        const float* inf = (s == 0) ? inf0 : (s == 1) ? inf1 : inf2;
        int   g   = 64 >> s;
        float str = strides[s];

        // each lane owns one sibling target of the same batch
        int tt = (b << 5) + lane;
        float xl = targets[tt * 5 + 0];
        float yl = targets[tt * 5 + 1];
        float wl = targets[tt * 5 + 2];
        float hl = targets[tt * 5 + 3];
        float cll = targets[tt * 5 + 4];

        float txl = xl / str, tyl = yl / str;
        float cilf = floorf(txl), cjlf = floorf(tyl);
        float fxl = txl - cilf,  fyl = tyl - cjlf;
        float twl = wl / str,    thl = hl / str;
        int   cil = (int)cilf,   cjl = (int)cjlf;

        // broadcast the warp's own target (lane t_local) to all lanes
        float fx = __shfl_sync(FULL, fxl, t_local);
        float fy = __shfl_sync(FULL, fyl, t_local);
        float tw = __shfl_sync(FULL, twl, t_local);
        float th = __shfl_sync(FULL, thl, t_local);
        int   ci = __shfl_sync(FULL, cil, t_local);
        int   cj = __shfl_sync(FULL, cjl, t_local);
        int   cls = (int)__shfl_sync(FULL, cll, t_local);

        float t_x0 = fx - 0.5f * tw, t_x1 = fx + 0.5f * tw;
        float t_y0 = fy - 0.5f * th, t_y1 = fy + 0.5f * th;
        float t_area = tw * th;

        // lane target rect (for sibling match + ownership test)
        float l_x0 = fxl - 0.5f * twl, l_x1 = fxl + 0.5f * twl;
        float l_y0 = fyl - 0.5f * thl, l_y1 = fyl + 0.5f * thl;
        float l_area = twl * thl;

        float boxsum = 0.0f, clssum = 0.0f, corr = 0.0f;
        int cnt = 0;

        #pragma unroll
        for (int a = 0; a < NAq; a++) {
            float aw = anchors[(s * NAq + a) * 2 + 0] / str;
            float ah = anchors[(s * NAq + a) * 2 + 1] / str;
            float a_x0 = 0.5f - 0.5f * aw, a_x1 = 0.5f + 0.5f * aw;
            float a_y0 = 0.5f - 0.5f * ah, a_y1 = 0.5f + 0.5f * ah;

            // every lane: IoU of ITS sibling target vs this anchor
            float x0 = fmaxf(l_x0, a_x0), y0 = fmaxf(l_y0, a_y0);
            float x1 = fminf(l_x1, a_x1), y1 = fminf(l_y1, a_y1);
            float inter = (x0 < x1 && y0 < y1) ? (x1 - x0) * (y1 - y0) : 0.0f;
            float iou = inter / (l_area + aw * ah - inter);
            bool  m_l = iou > 0.5f;

            unsigned ball = __ballot_sync(FULL, m_l);
            if ((ball >> t_local) & 1) {            // warp's target matched (uniform)
                cnt++;
                const float* pred = inf + (((long)(b * NAq + a) * g + cj) * g + ci) * 85;

                // ownership: is any smaller-index sibling matched at the SAME cell?
                unsigned cellb = __ballot_sync(FULL, m_l && (cil == ci) && (cjl == cj));
                bool owner = (cellb & ((1u << t_local) - 1u)) == 0u;

                if (lane == 0) {
                    float p0 = pred[0], p1 = pred[1], p2 = pred[2], p3 = pred[3], p4 = pred[4];
                    float pxc = sigmoidf(p0), pyc = sigmoidf(p1);
                    float pw = fminf(expf(p2), 1000.0f) * aw;
                    float ph = fminf(expf(p3), 1000.0f) * ah;
                    float p_x0 = pxc - 0.5f * pw, p_x1 = pxc + 0.5f * pw;
                    float p_y0 = pyc - 0.5f * ph, p_y1 = pyc + 0.5f * ph;
                    float ix0 = fmaxf(p_x0, t_x0), iy0 = fmaxf(p_y0, t_y0);
                    float ix1 = fminf(p_x1, t_x1), iy1 = fminf(p_y1, t_y1);
                    float pint = (ix0 < ix1 && iy0 < iy1) ? (ix1 - ix0) * (iy1 - iy0) : 0.0f;
                    float uni = pw * ph + t_area - pint;
                    boxsum += 1.0f - pint / uni;
                    if (owner) corr -= p4;          // softplus(-p) - softplus(p) = -p
                }

                // cls BCE across lanes (c = lane, lane+32, lane+64)
                #pragma unroll
                for (int k = 0; k < 3; k++) {
                    int c = lane + k * 32;
                    if (c < NCLS) {
                        float p = pred[5 + c];
                        clssum += (c == cls) ? softplusf(-p) : softplusf(p);
                    }
                }
            }
        }

        #pragma unroll
        for (int o = 16; o; o >>= 1)
            clssum += __shfl_xor_sync(FULL, clssum, o);

        if (lane == 0 && cnt > 0) {
            atomicAdd(&g_acc[s],     (float)cnt);
            atomicAdd(&g_acc[3 + s], boxsum);
            atomicAdd(&g_acc[6 + s], clssum);
            atomicAdd(&g_acc[9 + s], corr);
        }
    }

    // ================= block reduce objectness sums ========================
    #pragma unroll
    for (int o = 16; o; o >>= 1) {
        obj0 += __shfl_xor_sync(FULL, obj0, o);
        obj1 += __shfl_xor_sync(FULL, obj1, o);
        obj2 += __shfl_xor_sync(FULL, obj2, o);
    }
    __shared__ float sh[3];
    if (threadIdx.x < 3) sh[threadIdx.x] = 0.0f;
    __syncthreads();
    if (lane == 0) {
        atomicAdd(&sh[0], obj0);
        atomicAdd(&sh[1], obj1);
        atomicAdd(&sh[2], obj2);
    }
    __syncthreads();
    if (threadIdx.x < 3) atomicAdd(&g_acc[9 + threadIdx.x], sh[threadIdx.x]);

    // ================= last-block fold + self-reset ========================
    __threadfence();
    __syncthreads();
    if (threadIdx.x == 0) {
        unsigned d = atomicAdd(&g_done, 1u);
        if (d == gridDim.x - 1) {
            __threadfence();
            volatile float* acc = g_acc;
            const float cells[3] = {(float)CELLS0, (float)CELLS1, (float)CELLS2};
            float box = 0.0f, obj = 0.0f, clsv = 0.0f;
            #pragma unroll
            for (int s = 0; s < 3; s++) {
                float cnt = fmaxf(acc[s], 1.0f);
                box  += acc[3 + s] / cnt;
                clsv += acc[6 + s] / (cnt * (float)NCLS);
                obj  += acc[9 + s] / cells[s];
            }
            out[0] = 3.54f * box + 64.3f * obj + 37.4f * clsv;
            #pragma unroll
            for (int i = 0; i < 12; i++) g_acc[i] = 0.0f;   // reset for next replay
            g_done = 0u;
        }
    }
}

// ---------------------------------------------------------------------------
extern "C" void kernel_launch(void* const* d_in, const int* in_sizes, int n_in,
                              void* d_out, int out_size)
{
    const float* inf0    = (const float*)d_in[0];
    const float* inf1    = (const float*)d_in[1];
    const float* inf2    = (const float*)d_in[2];
    const float* anchors = (const float*)d_in[3];
    const float* strides = (const float*)d_in[4];
    const float* targets = (const float*)d_in[5];
    float* out = (float*)d_out;

    yolo_fused<<<NBLOCKS, BLK>>>(inf0, inf1, inf2, anchors, strides, targets, out);
}